// round 1
// baseline (speedup 1.0000x reference)
#include <cuda_runtime.h>

#define NN   1024
#define OUTN 513
#define NIMG 48
#define TR   16
#define TC   64
#define ICOLS (2*TC + 2)   /* 130 input cols needed per tile */
#define SW    (ICOLS + 2)  /* smem row pitch 132 */

__device__ __forceinline__ int symc(int i) {
    // symmetric ('reflect-including-edge') index, single reflection is
    // sufficient: |overshoot| <= TR*2+1 + 3 << NN
    i = (i < 0)     ? (-1 - i)       : i;
    i = (i >= NN)   ? (2*NN - 1 - i) : i;
    return i;
}

// filters reversed (true convolution): fr[k] = DEC[3-k]
__constant__ float FR_LO[4] = { 0.48296291314469025f,  0.836516303737469f,
                                0.22414386804185735f, -0.12940952255092145f };
__constant__ float FR_HI[4] = {-0.12940952255092145f, -0.22414386804185735f,
                                0.836516303737469f,   -0.48296291314469025f };

__global__ __launch_bounds__(256)
void dwt2_kernel(const float* __restrict__ x, float* __restrict__ out) {
    __shared__ float lo_v[TR][SW];
    __shared__ float hi_v[TR][SW];

    const int z  = blockIdx.z;
    const int r0 = blockIdx.y * TR;   // output-row tile origin
    const int c0 = blockIdx.x * TC;   // output-col tile origin
    const float* __restrict__ img = x + (size_t)z * NN * NN;
    const int tid = threadIdx.x;

    // ---- Phase 1: vertical DWT (axis -2) into shared memory ----
    // For each (local out-row lr, local in-col j) compute
    //   lo_v[lr][j] = sum_k FR_LO[k] * X[sym(2*(r0+lr)-2+k)][sym(2*c0-2+j)]
    //   hi_v[lr][j] = sum_k FR_HI[k] * (same inputs)
    #pragma unroll 1
    for (int idx = tid; idx < TR * ICOLS; idx += 256) {
        int lr = idx / ICOLS;            // const divisor -> mul
        int j  = idx - lr * ICOLS;
        int xi = symc(2*c0 - 2 + j);
        int rb = 2*(r0 + lr) - 2;
        float v0 = img[(size_t)symc(rb + 0) * NN + xi];
        float v1 = img[(size_t)symc(rb + 1) * NN + xi];
        float v2 = img[(size_t)symc(rb + 2) * NN + xi];
        float v3 = img[(size_t)symc(rb + 3) * NN + xi];
        lo_v[lr][j] = FR_LO[0]*v0 + FR_LO[1]*v1 + FR_LO[2]*v2 + FR_LO[3]*v3;
        hi_v[lr][j] = FR_HI[0]*v0 + FR_HI[1]*v1 + FR_HI[2]*v2 + FR_HI[3]*v3;
    }
    __syncthreads();

    // ---- Phase 2: horizontal DWT (axis -1, lo filter for both outputs) ----
    float* __restrict__ cA = out;
    float* __restrict__ cH = out + (size_t)NIMG * OUTN * OUTN;

    #pragma unroll
    for (int idx = tid; idx < TR * TC; idx += 256) {
        int lr = idx >> 6;       // /TC (=64)
        int lc = idx & (TC - 1);
        int r = r0 + lr;
        int c = c0 + lc;
        if (r < OUTN && c < OUTN) {
            int jb = 2 * lc;     // local smem col base (halo already included)
            float a = FR_LO[0]*lo_v[lr][jb+0] + FR_LO[1]*lo_v[lr][jb+1]
                    + FR_LO[2]*lo_v[lr][jb+2] + FR_LO[3]*lo_v[lr][jb+3];
            float h = FR_LO[0]*hi_v[lr][jb+0] + FR_LO[1]*hi_v[lr][jb+1]
                    + FR_LO[2]*hi_v[lr][jb+2] + FR_LO[3]*hi_v[lr][jb+3];
            size_t base = ((size_t)z * OUTN + r) * OUTN + c;
            cA[base] = a;
            cH[base] = h;
        }
    }
}

extern "C" void kernel_launch(void* const* d_in, const int* in_sizes, int n_in,
                              void* d_out, int out_size) {
    const float* x = (const float*)d_in[0];
    float* out = (float*)d_out;
    dim3 grid((OUTN + TC - 1) / TC,    // 9
              (OUTN + TR - 1) / TR,    // 33
              NIMG);                   // 48
    dwt2_kernel<<<grid, 256>>>(x, out);
}

// round 2
// speedup vs baseline: 1.2569x; 1.2569x over previous
#include <cuda_runtime.h>

#define NN    1024
#define OUTN  513
#define NIMG  48
#define TR    16          /* output rows per tile  */
#define TC    128         /* output cols per tile  */
#define ICOLS (2*TC + 2)  /* 258 input cols per full tile */

__device__ __forceinline__ int symc(int i) {
    // symmetric (reflect-including-edge); single reflection suffices here
    i = (i < 0)   ? (-1 - i)       : i;
    i = (i >= NN) ? (2*NN - 1 - i) : i;
    return i;
}

// filters reversed (true convolution): fr[k] = DEC[3-k]
#define FL0 ( 0.48296291314469025f)
#define FL1 ( 0.836516303737469f)
#define FL2 ( 0.22414386804185735f)
#define FL3 (-0.12940952255092145f)
#define FH0 (-0.12940952255092145f)
#define FH1 (-0.22414386804185735f)
#define FH2 ( 0.836516303737469f)
#define FH3 (-0.48296291314469025f)

__global__ __launch_bounds__(256)
void dwt2_kernel(const float* __restrict__ x, float* __restrict__ out) {
    __shared__ __align__(16) float lo_v[TR][ICOLS];
    __shared__ __align__(16) float hi_v[TR][ICOLS];

    const int z  = blockIdx.z;
    const int r0 = blockIdx.y * TR;
    const int c0 = blockIdx.x * TC;
    const float* __restrict__ img = x + (size_t)z * NN * NN;
    const int tid = threadIdx.x;

    const int ncols = min(TC, OUTN - c0);
    const int icols = 2 * ncols + 2;          // input cols actually needed
    const int rb0   = 2 * r0 - 2;             // first input row of tile
    const bool rowfast = (rb0 >= 0) && (rb0 + 2*TR + 1 < NN);

    // ---- Phase 1: vertical DWT, column-stationary with rolling row reuse ----
    for (int j = tid; j < icols; j += 256) {
        const int xi = symc(2*c0 - 2 + j);    // column index: computed ONCE
        if (rowfast) {
            const float* p = img + (size_t)rb0 * NN + xi;
            float a = p[0];
            float b = p[NN];
            p += 2 * NN;
            #pragma unroll
            for (int lr = 0; lr < TR; ++lr) {
                float c = p[0];
                float d = p[NN];
                lo_v[lr][j] = FL0*a + FL1*b + FL2*c + FL3*d;
                hi_v[lr][j] = FH0*a + FH1*b + FH2*c + FH3*d;
                a = c; b = d;
                p += 2 * NN;
            }
        } else {
            float a = img[(size_t)symc(rb0)     * NN + xi];
            float b = img[(size_t)symc(rb0 + 1) * NN + xi];
            #pragma unroll
            for (int lr = 0; lr < TR; ++lr) {
                float c = img[(size_t)symc(rb0 + 2*lr + 2) * NN + xi];
                float d = img[(size_t)symc(rb0 + 2*lr + 3) * NN + xi];
                lo_v[lr][j] = FL0*a + FL1*b + FL2*c + FL3*d;
                hi_v[lr][j] = FH0*a + FH1*b + FH2*c + FH3*d;
                a = c; b = d;
            }
        }
    }
    __syncthreads();

    // ---- Phase 2: horizontal DWT (lo filter on both lo_v and hi_v) ----
    float* __restrict__ cA = out;
    float* __restrict__ cH = out + (size_t)NIMG * OUTN * OUTN;

    const int lc  = tid & (TC - 1);   // fixed column per thread
    const int lr0 = tid >> 7;         // 0 or 1
    const int c   = c0 + lc;

    if (c < OUTN) {
        const int jb = 2 * lc;
        #pragma unroll
        for (int i = 0; i < TR / 2; ++i) {
            const int lr = lr0 + 2 * i;
            const int r  = r0 + lr;
            if (r < OUTN) {
                float2 l01 = *(const float2*)&lo_v[lr][jb];
                float2 l23 = *(const float2*)&lo_v[lr][jb + 2];
                float2 h01 = *(const float2*)&hi_v[lr][jb];
                float2 h23 = *(const float2*)&hi_v[lr][jb + 2];
                float a = FL0*l01.x + FL1*l01.y + FL2*l23.x + FL3*l23.y;
                float h = FL0*h01.x + FL1*h01.y + FL2*h23.x + FL3*h23.y;
                size_t base = ((size_t)z * OUTN + r) * OUTN + c;
                cA[base] = a;
                cH[base] = h;
            }
        }
    }
}

extern "C" void kernel_launch(void* const* d_in, const int* in_sizes, int n_in,
                              void* d_out, int out_size) {
    const float* x = (const float*)d_in[0];
    float* out = (float*)d_out;
    dim3 grid((OUTN + TC - 1) / TC,    // 5
              (OUTN + TR - 1) / TR,    // 33
              NIMG);                   // 48
    dwt2_kernel<<<grid, 256>>>(x, out);
}

// round 3
// speedup vs baseline: 1.9103x; 1.5198x over previous
#include <cuda_runtime.h>

#define NN    1024
#define OUTN  513
#define NIMG  48
#define TR    8            /* output rows per tile  */
#define TC    127          /* output cols per tile  */
#define ICOLS 256          /* = 2*TC + 2 : input cols per full tile */

__device__ __forceinline__ int symc(int i) {
    i = (i < 0)   ? (-1 - i)       : i;
    i = (i >= NN) ? (2*NN - 1 - i) : i;
    return i;
}

// filters reversed (true convolution): fr[k] = DEC[3-k]
#define FL0 ( 0.48296291314469025f)
#define FL1 ( 0.836516303737469f)
#define FL2 ( 0.22414386804185735f)
#define FL3 (-0.12940952255092145f)
#define FH0 (-0.12940952255092145f)
#define FH1 (-0.22414386804185735f)
#define FH2 ( 0.836516303737469f)
#define FH3 (-0.48296291314469025f)

__global__ __launch_bounds__(256, 6)
void dwt2_kernel(const float* __restrict__ x, float* __restrict__ out) {
    // interleaved (lo, hi) per vertical-transform element
    __shared__ __align__(16) float2 s[TR][ICOLS];

    const int z  = blockIdx.z;
    const int r0 = blockIdx.y * TR;
    const int c0 = blockIdx.x * TC;
    const float* __restrict__ img = x + (size_t)z * NN * NN;
    const int tid = threadIdx.x;

    const int ncols = min(TC, OUTN - c0);
    const int icols = 2 * ncols + 2;          // input cols actually needed
    const int rb0   = 2 * r0 - 2;             // first input row of tile
    const bool rowfast = (rb0 >= 0) && (rb0 + 2*TR + 1 < NN);

    // ---- Phase 1: vertical DWT, column-stationary, rolling row reuse ----
    for (int j = tid; j < icols; j += 256) {
        const int xi = symc(2*c0 - 2 + j);    // column index computed once
        if (rowfast) {
            const float* p = img + (size_t)rb0 * NN + xi;
            float a = p[0];
            float b = p[NN];
            p += 2 * NN;
            #pragma unroll
            for (int lr = 0; lr < TR; ++lr) {
                float c = p[0];
                float d = p[NN];
                s[lr][j] = make_float2(FL0*a + FL1*b + FL2*c + FL3*d,
                                       FH0*a + FH1*b + FH2*c + FH3*d);
                a = c; b = d;
                p += 2 * NN;
            }
        } else {
            float a = img[(size_t)symc(rb0)     * NN + xi];
            float b = img[(size_t)symc(rb0 + 1) * NN + xi];
            #pragma unroll
            for (int lr = 0; lr < TR; ++lr) {
                float c = img[(size_t)symc(rb0 + 2*lr + 2) * NN + xi];
                float d = img[(size_t)symc(rb0 + 2*lr + 3) * NN + xi];
                s[lr][j] = make_float2(FL0*a + FL1*b + FL2*c + FL3*d,
                                       FH0*a + FH1*b + FH2*c + FH3*d);
                a = c; b = d;
            }
        }
    }
    __syncthreads();

    // ---- Phase 2: horizontal DWT (lo filter on both lanes) ----
    float* __restrict__ cA = out;
    float* __restrict__ cH = out + (size_t)NIMG * OUTN * OUTN;

    const int lc  = tid & 127;        // column within tile (0..127; 127 idle)
    const int lr0 = tid >> 7;         // 0 or 1
    const int c   = c0 + lc;

    if (lc < TC && c < OUTN) {
        const int jb = 2 * lc;
        #pragma unroll
        for (int i = 0; i < TR / 2; ++i) {
            const int lr = lr0 + 2 * i;
            const int r  = r0 + lr;
            if (r < OUTN) {
                float4 q0 = *(const float4*)&s[lr][jb];      // lo0,hi0,lo1,hi1
                float4 q1 = *(const float4*)&s[lr][jb + 2];  // lo2,hi2,lo3,hi3
                float a = FL0*q0.x + FL1*q0.z + FL2*q1.x + FL3*q1.z;
                float h = FL0*q0.y + FL1*q0.w + FL2*q1.y + FL3*q1.w;
                size_t base = ((size_t)z * OUTN + r) * OUTN + c;
                cA[base] = a;
                cH[base] = h;
            }
        }
    }
}

extern "C" void kernel_launch(void* const* d_in, const int* in_sizes, int n_in,
                              void* d_out, int out_size) {
    const float* x = (const float*)d_in[0];
    float* out = (float*)d_out;
    dim3 grid((OUTN + TC - 1) / TC,    // 5
              (OUTN + TR - 1) / TR,    // 65
              NIMG);                   // 48
    dwt2_kernel<<<grid, 256>>>(x, out);
}